// round 3
// baseline (speedup 1.0000x reference)
#include <cuda_runtime.h>
#include <math.h>

#define NB 32
#define NA 8400
#define NG 100
#define BA (NB*NA)
#define NBLK3 (33*32)
#define TS 256          // k2 smem tile entries

// ---- device scratch (static globals; zero-initialized at load) ----
__device__ int    g_cnt[BA];      // per-anchor match count
__device__ float  g_miou[BA];     // matched-pair iou (valid when cnt==1)
__device__ int    g_nfg[NB];      // per-image fg count (re-zeroed by k4)
__device__ int    g_cidx[BA];     // compacted: original anchor index
__device__ float4 g_cbox[BA];     // compacted: pred bbox cxcywh
__device__ float4 g_cgeo[BA];     // compacted: xc, yc, r, clsc
__device__ float  g_psum[NBLK3];
__device__ int    g_pcnt[NBLK3];

__device__ __forceinline__ float softplus(float x){
    return fmaxf(x, 0.0f) + log1pf(expf(-fabsf(x)));
}

// ---------------------------------------------------------------------------
// Kernel 1: fg mask + compaction. Valid GTs pre-compacted into smem.
// ---------------------------------------------------------------------------
__global__ void k1_fg_compact(const float* __restrict__ outputs,
                              const float* __restrict__ labels,
                              const float* __restrict__ xs,
                              const float* __restrict__ ys,
                              const float* __restrict__ st){
    __shared__ float4 sgt[NG];     // x0,y0,x1,y1
    __shared__ float2 scen[NG];    // gcx,gcy
    __shared__ int    snv;
    __shared__ int    wcnt[8], wbase[8], blkbase;

    int b = blockIdx.y;
    if (threadIdx.x == 0) snv = 0;
    __syncthreads();
    if (threadIdx.x < NG){
        const float* L = labels + (size_t)(b*NG + threadIdx.x)*5;
        float l0=L[0], gcx=L[1], gcy=L[2], gw=L[3], gh=L[4];
        if ((l0+gcx+gcy+gw+gh) > 0.0f){
            int p = atomicAdd(&snv, 1);
            sgt[p]  = make_float4(gcx - gw*0.5f, gcy - gh*0.5f,
                                  gcx + gw*0.5f, gcy + gh*0.5f);
            scen[p] = make_float2(gcx, gcy);
        }
    }
    __syncthreads();
    int nv = snv;

    int a = blockIdx.x*blockDim.x + threadIdx.x;
    bool fg = false;
    float xc=0.f, yc=0.f, r=0.f;
    if (a < NA){
        float s  = st[a];
        xc = (xs[a] + 0.5f) * s;
        yc = (ys[a] + 0.5f) * s;
        r  = 2.5f * s;
        for (int g = 0; g < nv; g++){
            float4 bx = sgt[g];
            float2 cn = scen[g];
            bool ib = (xc > bx.x) && (xc < bx.z) && (yc > bx.y) && (yc < bx.w);
            bool ic = (fabsf(xc - cn.x) < r) && (fabsf(yc - cn.y) < r);
            if (ib || ic){ fg = true; break; }
        }
        g_cnt[b*NA + a] = 0;
    }

    unsigned ball = __ballot_sync(0xffffffffu, fg);
    int wid = threadIdx.x >> 5, lane = threadIdx.x & 31;
    if (lane == 0) wcnt[wid] = __popc(ball);
    __syncthreads();
    if (threadIdx.x == 0){
        int tot = 0;
        #pragma unroll
        for (int i = 0; i < 8; i++){ wbase[i] = tot; tot += wcnt[i]; }
        blkbase = tot ? atomicAdd(&g_nfg[b], tot) : 0;
    }
    __syncthreads();

    if (fg){
        int idx = b*NA + a;
        const float* o = outputs + (size_t)idx*6;
        float2 c2 = *(const float2*)(o);
        float2 w2 = *(const float2*)(o + 2);
        float2 oc = *(const float2*)(o + 4);
        float sig_o = 1.0f/(1.0f + expf(-oc.x));
        float sig_c = 1.0f/(1.0f + expf(-oc.y));
        float clsc = -logf(sqrtf(sig_c * sig_o) + 1e-9f);
        int pos = b*NA + blkbase + wbase[wid] + __popc(ball & ((1u << lane) - 1u));
        g_cidx[pos] = a;
        g_cbox[pos] = make_float4(c2.x, c2.y, w2.x, w2.y);
        g_cgeo[pos] = make_float4(xc, yc, r, clsc);
    }
}

// ---------------------------------------------------------------------------
// Kernel 2: 4 warps/block = 4 GTs of one image; smem-tiled fg scan.
// ---------------------------------------------------------------------------
__global__ void k2_assign(const float* __restrict__ labels){
    __shared__ int    sidx[TS];
    __shared__ float4 sbox[TS];
    __shared__ float4 sgeo[TS];

    int b    = blockIdx.y;
    int g    = blockIdx.x*4 + (threadIdx.x >> 5);
    int lane = threadIdx.x & 31;

    const float* L = labels + (size_t)(b*NG + g)*5;
    float l0=L[0], gcx=L[1], gcy=L[2], gw=L[3], gh=L[4];
    bool validgt = ((l0+gcx+gcy+gw+gh) > 0.0f);

    float gl = gcx - gw*0.5f, gr_ = gcx + gw*0.5f;
    float gt_ = gcy - gh*0.5f, gb = gcy + gh*0.5f;
    float garea = gw*gh;

    int nfg = g_nfg[b];
    const int*    cidx = g_cidx + b*NA;
    const float4* cbox = g_cbox + b*NA;
    const float4* cgeo = g_cgeo + b*NA;

    float tc[10]; int ti[10]; float tv[10]; float tu[10];
    #pragma unroll
    for (int k=0;k<10;k++){ tc[k]=3e38f; ti[k]=0x7fffffff; tv[k]=0.0f; tu[k]=0.0f; }

    for (int base = 0; base < nfg; base += TS){
        int cnt = min(TS, nfg - base);
        __syncthreads();
        for (int i = threadIdx.x; i < cnt; i += 128){
            sidx[i] = cidx[base + i];
            sbox[i] = cbox[base + i];
            sgeo[i] = cgeo[base + i];
        }
        __syncthreads();
        if (!validgt) continue;

        for (int j = lane; j < cnt; j += 32){
            float4 bb = sbox[j];
            float4 ge = sgeo[j];
            int    a  = sidx[j];
            float tlx = fmaxf(gl,  bb.x - bb.z*0.5f);
            float tly = fmaxf(gt_, bb.y - bb.w*0.5f);
            float brx = fminf(gr_, bb.x + bb.z*0.5f);
            float bry = fminf(gb,  bb.y + bb.w*0.5f);
            float iw = fmaxf(brx - tlx, 0.0f);
            float ih = fmaxf(bry - tly, 0.0f);
            float inter = iw*ih;
            float iou = inter / (garea + bb.z*bb.w - inter + 1e-12f);
            bool ib = (ge.x > gl) && (ge.x < gr_) && (ge.y > gt_) && (ge.y < gb);
            bool ic = (fabsf(ge.x - gcx) < ge.z) && (fabsf(ge.y - gcy) < ge.z);
            bool geo = ib && ic;
            float cost = ge.w - 3.0f*logf(iou + 1e-8f) + (geo ? 0.0f : 100000.0f);

            if (iou > tu[9]){
                float v = iou;
                #pragma unroll
                for (int k=0;k<10;k++){
                    if (v > tu[k]){ float t = tu[k]; tu[k] = v; v = t; }
                }
            }
            if (cost < tc[9] || (cost == tc[9] && a < ti[9])){
                float cc = cost; int ii = a; float vv = iou;
                #pragma unroll
                for (int k=0;k<10;k++){
                    bool lt = (cc < tc[k]) || (cc == tc[k] && ii < ti[k]);
                    if (lt){
                        float t0=tc[k]; tc[k]=cc; cc=t0;
                        int   t1=ti[k]; ti[k]=ii; ii=t1;
                        float t2=tv[k]; tv[k]=vv; vv=t2;
                    }
                }
            }
        }
    }

    if (!validgt) return;

    const unsigned FULL = 0xffffffffu;
    float su = 0.0f;
    #pragma unroll
    for (int r = 0; r < 10; r++){
        float bv = tu[0];
        int   bl = lane;
        #pragma unroll
        for (int off = 16; off; off >>= 1){
            float ov = __shfl_down_sync(FULL, bv, off);
            int   ol = __shfl_down_sync(FULL, bl, off);
            if (ov > bv){ bv = ov; bl = ol; }
        }
        bv = __shfl_sync(FULL, bv, 0);
        bl = __shfl_sync(FULL, bl, 0);
        if (lane == bl){
            #pragma unroll
            for (int k=0;k<9;k++) tu[k] = tu[k+1];
            tu[9] = 0.0f;
        }
        su += bv;
    }
    int dynk = (int)su;
    if (dynk < 1) dynk = 1;

    for (int r = 0; r < dynk; r++){
        float bc  = tc[0];
        int   bi  = ti[0];
        float bvv = tv[0];
        int   bl  = lane;
        #pragma unroll
        for (int off = 16; off; off >>= 1){
            float oc = __shfl_down_sync(FULL, bc,  off);
            int   oi = __shfl_down_sync(FULL, bi,  off);
            float ov = __shfl_down_sync(FULL, bvv, off);
            int   ol = __shfl_down_sync(FULL, bl,  off);
            if (oc < bc || (oc == bc && oi < bi)){ bc=oc; bi=oi; bvv=ov; bl=ol; }
        }
        bc  = __shfl_sync(FULL, bc,  0);
        bi  = __shfl_sync(FULL, bi,  0);
        bvv = __shfl_sync(FULL, bvv, 0);
        bl  = __shfl_sync(FULL, bl,  0);
        if (bc >= 1e9f) break;
        if (lane == bl){
            #pragma unroll
            for (int k=0;k<9;k++){ tc[k]=tc[k+1]; ti[k]=ti[k+1]; tv[k]=tv[k+1]; }
            tc[9] = 3e38f; ti[9] = 0x7fffffff; tv[9] = 0.0f;
        }
        if (lane == 0){
            atomicAdd(&g_cnt[b*NA + bi], 1);
            g_miou[b*NA + bi] = bvv;   // raced only when cnt>1 (then unused)
        }
    }
}

// ---------------------------------------------------------------------------
// Kernel 3: loss over compacted fg entries only. cnt>1 recompute self-consistent.
// ---------------------------------------------------------------------------
__global__ void k3_loss(const float* __restrict__ outputs,
                        const float* __restrict__ labels){
    __shared__ float4 sgt[NG];     // x0,y0,x1,y1
    __shared__ float2 scen[NG];    // gcx,gcy
    __shared__ float  sarea[NG];
    __shared__ int    snv;
    __shared__ float  ssum[256];
    __shared__ int    scnt[256];

    int b = blockIdx.y;
    if (threadIdx.x == 0) snv = 0;
    __syncthreads();
    if (threadIdx.x < NG){
        const float* L = labels + (size_t)(b*NG + threadIdx.x)*5;
        float l0=L[0], gcx=L[1], gcy=L[2], gw=L[3], gh=L[4];
        if ((l0+gcx+gcy+gw+gh) > 0.0f){
            int p = atomicAdd(&snv, 1);
            sgt[p]   = make_float4(gcx - gw*0.5f, gcy - gh*0.5f,
                                   gcx + gw*0.5f, gcy + gh*0.5f);
            scen[p]  = make_float2(gcx, gcy);
            sarea[p] = gw*gh;
        }
    }
    __syncthreads();
    int nv = snv;

    int nfg = g_nfg[b];
    int j = blockIdx.x*blockDim.x + threadIdx.x;
    float term = 0.0f;
    int   isfg = 0;
    if (j < nfg){
        int a   = g_cidx[b*NA + j];
        int cnt = g_cnt[b*NA + a];
        if (cnt >= 1){
            isfg = 1;
            float pred_iou;
            if (cnt == 1){
                pred_iou = g_miou[b*NA + a];
            } else {
                float4 bb = g_cbox[b*NA + j];
                float4 ge = g_cgeo[b*NA + j];
                float barea = bb.z*bb.w;
                float bestc = 3e38f, besti = 0.0f;
                for (int g = 0; g < nv; g++){
                    float4 bx = sgt[g];
                    float2 cn = scen[g];
                    float tlx = fmaxf(bx.x, bb.x - bb.z*0.5f);
                    float tly = fmaxf(bx.y, bb.y - bb.w*0.5f);
                    float brx = fminf(bx.z, bb.x + bb.z*0.5f);
                    float bry = fminf(bx.w, bb.y + bb.w*0.5f);
                    float iw = fmaxf(brx - tlx, 0.0f);
                    float ih = fmaxf(bry - tly, 0.0f);
                    float inter = iw*ih;
                    float iou = inter / (sarea[g] + barea - inter + 1e-12f);
                    bool ib = (ge.x > bx.x) && (ge.x < bx.z) &&
                              (ge.y > bx.y) && (ge.y < bx.w);
                    bool ic = (fabsf(ge.x - cn.x) < ge.z) && (fabsf(ge.y - cn.y) < ge.z);
                    bool geo = ib && ic;
                    float cost = ge.w - 3.0f*logf(iou + 1e-8f) + (geo ? 0.0f : 100000.0f);
                    if (cost < bestc){ bestc = cost; besti = iou; }
                }
                pred_iou = besti;
            }
            float x = outputs[(size_t)(b*NA + a)*6 + 5];
            float sp_p = softplus(x);
            float sp_n = softplus(-x);
            term = pred_iou*sp_n + (1.0f - pred_iou)*sp_p;
        }
    }
    ssum[threadIdx.x] = term;
    scnt[threadIdx.x] = isfg;
    __syncthreads();
    for (int o = 128; o; o >>= 1){
        if (threadIdx.x < o){
            ssum[threadIdx.x] += ssum[threadIdx.x + o];
            scnt[threadIdx.x] += scnt[threadIdx.x + o];
        }
        __syncthreads();
    }
    if (threadIdx.x == 0){
        int blk = blockIdx.y*gridDim.x + blockIdx.x;
        g_psum[blk] = ssum[0];
        g_pcnt[blk] = scnt[0];
    }
}

// ---------------------------------------------------------------------------
// Kernel 4: fixed-order final reduce + re-zero g_nfg for next replay.
// ---------------------------------------------------------------------------
__global__ void k4_final(float* __restrict__ out){
    __shared__ float ss[256];
    __shared__ int   sc[256];
    float s = 0.0f; int c = 0;
    for (int i = threadIdx.x; i < NBLK3; i += 256){ s += g_psum[i]; c += g_pcnt[i]; }
    ss[threadIdx.x] = s; sc[threadIdx.x] = c;
    __syncthreads();
    for (int o = 128; o; o >>= 1){
        if (threadIdx.x < o){ ss[threadIdx.x] += ss[threadIdx.x+o]; sc[threadIdx.x] += sc[threadIdx.x+o]; }
        __syncthreads();
    }
    if (threadIdx.x == 0){
        float nf = (float)sc[0];
        if (nf < 1.0f) nf = 1.0f;
        out[0] = ss[0] / nf;
    }
    if (threadIdx.x < NB) g_nfg[threadIdx.x] = 0;   // restore state for next replay
}

extern "C" void kernel_launch(void* const* d_in, const int* in_sizes, int n_in,
                              void* d_out, int out_size){
    const float* outputs = (const float*)d_in[0];  // [32, 8400, 6]
    const float* labels  = (const float*)d_in[1];  // [32, 100, 5]
    const float* xs      = (const float*)d_in[2];  // [1, 8400]
    const float* ys      = (const float*)d_in[3];  // [1, 8400]
    const float* st      = (const float*)d_in[4];  // [1, 8400]

    dim3 ganchor(33, NB);
    k1_fg_compact<<<ganchor, 256>>>(outputs, labels, xs, ys, st);
    k2_assign<<<dim3(NG/4, NB), 128>>>(labels);
    k3_loss<<<ganchor, 256>>>(outputs, labels);
    k4_final<<<1, 256>>>((float*)d_out);
}

// round 4
// speedup vs baseline: 1.0144x; 1.0144x over previous
#include <cuda_runtime.h>
#include <math.h>

#define NB 32
#define NA 8400
#define NG 100
#define BA (NB*NA)
#define NBLK3 (33*32)
#define TS 256          // k2 smem tile entries

// ---- device scratch (static globals; zero-initialized at load) ----
__device__ int    g_cnt[BA];      // per-anchor match count
__device__ float  g_miou[BA];     // matched-pair iou (valid when cnt==1)
__device__ int    g_nfg[NB];      // per-image fg count (reset by k3 last block)
__device__ int    g_cidx[BA];     // compacted: original anchor index
__device__ float4 g_cbox[BA];     // compacted: pred bbox cxcywh
__device__ float4 g_cgeo[BA];     // compacted: xc, yc, r, clsc
__device__ float  g_psum[NBLK3];
__device__ int    g_pcnt[NBLK3];
__device__ int    g_done;         // k3 completion counter (reset by last block)

__device__ __forceinline__ float softplus(float x){
    return fmaxf(x, 0.0f) + log1pf(expf(-fabsf(x)));
}

// ---------------------------------------------------------------------------
// Kernel 1: fg mask + compaction, with per-block GT y-culling.
// ---------------------------------------------------------------------------
__global__ void k1_fg_compact(const float* __restrict__ outputs,
                              const float* __restrict__ labels,
                              const float* __restrict__ xs,
                              const float* __restrict__ ys,
                              const float* __restrict__ st){
    __shared__ float4 cgt[NG];     // culled GT: x0,y0,x1,y1
    __shared__ float2 ccen[NG];    // culled GT: gcx,gcy
    __shared__ int    scv;
    __shared__ float  rmn[8], rmx[8], rrm[8];
    __shared__ float  bymin, bymax, brmax;
    __shared__ int    wcnt[8], wbase[8], blkbase;

    int b = blockIdx.y;
    int a = blockIdx.x*blockDim.x + threadIdx.x;
    bool valid = (a < NA);
    float xc=0.f, yc=0.f, r=0.f;
    if (valid){
        float s  = st[a];
        xc = (xs[a] + 0.5f) * s;
        yc = (ys[a] + 0.5f) * s;
        r  = 2.5f * s;
    }

    // block reduce ymin/ymax/rmax over valid anchors
    int wid = threadIdx.x >> 5, lane = threadIdx.x & 31;
    {
        float mn = valid ? yc :  1e30f;
        float mx = valid ? yc : -1e30f;
        float rm = valid ? r  :  0.0f;
        #pragma unroll
        for (int off = 16; off; off >>= 1){
            mn = fminf(mn, __shfl_down_sync(0xffffffffu, mn, off));
            mx = fmaxf(mx, __shfl_down_sync(0xffffffffu, mx, off));
            rm = fmaxf(rm, __shfl_down_sync(0xffffffffu, rm, off));
        }
        if (lane == 0){ rmn[wid] = mn; rmx[wid] = mx; rrm[wid] = rm; }
    }
    if (threadIdx.x == 0) scv = 0;
    __syncthreads();
    if (threadIdx.x == 0){
        float mn = rmn[0], mx = rmx[0], rm = rrm[0];
        #pragma unroll
        for (int i = 1; i < 8; i++){
            mn = fminf(mn, rmn[i]); mx = fmaxf(mx, rmx[i]); rm = fmaxf(rm, rrm[i]);
        }
        bymin = mn; bymax = mx; brmax = rm;
    }
    __syncthreads();
    float ymin = bymin, ymax = bymax, rmaxb = brmax;

    // one-pass GT load + validity + y-cull + append
    if (threadIdx.x < NG){
        const float* L = labels + (size_t)(b*NG + threadIdx.x)*5;
        float l0=L[0], gcx=L[1], gcy=L[2], gw=L[3], gh=L[4];
        if ((l0+gcx+gcy+gw+gh) > 0.0f){
            float y0 = gcy - gh*0.5f, y1 = gcy + gh*0.5f;
            bool boxy = (ymax > y0) && (ymin < y1);
            bool ctry = (ymax > gcy - rmaxb) && (ymin < gcy + rmaxb);
            if (boxy || ctry){
                int p = atomicAdd(&scv, 1);
                cgt[p]  = make_float4(gcx - gw*0.5f, y0, gcx + gw*0.5f, y1);
                ccen[p] = make_float2(gcx, gcy);
            }
        }
    }
    __syncthreads();
    int cv = scv;

    bool fg = false;
    if (valid){
        for (int g = 0; g < cv; g++){
            float4 bx = cgt[g];
            float2 cn = ccen[g];
            bool ib = (xc > bx.x) && (xc < bx.z) && (yc > bx.y) && (yc < bx.w);
            bool ic = (fabsf(xc - cn.x) < r) && (fabsf(yc - cn.y) < r);
            if (ib || ic){ fg = true; break; }
        }
        g_cnt[b*NA + a] = 0;
    }

    unsigned ball = __ballot_sync(0xffffffffu, fg);
    if (lane == 0) wcnt[wid] = __popc(ball);
    __syncthreads();
    if (threadIdx.x == 0){
        int tot = 0;
        #pragma unroll
        for (int i = 0; i < 8; i++){ wbase[i] = tot; tot += wcnt[i]; }
        blkbase = tot ? atomicAdd(&g_nfg[b], tot) : 0;
    }
    __syncthreads();

    if (fg){
        int idx = b*NA + a;
        const float* o = outputs + (size_t)idx*6;
        float2 c2 = *(const float2*)(o);
        float2 w2 = *(const float2*)(o + 2);
        float2 oc = *(const float2*)(o + 4);
        float sig_o = 1.0f/(1.0f + expf(-oc.x));
        float sig_c = 1.0f/(1.0f + expf(-oc.y));
        float clsc = -logf(sqrtf(sig_c * sig_o) + 1e-9f);
        int pos = b*NA + blkbase + wbase[wid] + __popc(ball & ((1u << lane) - 1u));
        g_cidx[pos] = a;
        g_cbox[pos] = make_float4(c2.x, c2.y, w2.x, w2.y);
        g_cgeo[pos] = make_float4(xc, yc, r, clsc);
    }
}

// ---------------------------------------------------------------------------
// Kernel 2: 4 warps/block = 4 GTs of one image; smem-tiled fg scan.
// ---------------------------------------------------------------------------
__global__ void k2_assign(const float* __restrict__ labels){
    __shared__ int    sidx[TS];
    __shared__ float4 sbox[TS];
    __shared__ float4 sgeo[TS];

    int b    = blockIdx.y;
    int g    = blockIdx.x*4 + (threadIdx.x >> 5);
    int lane = threadIdx.x & 31;

    const float* L = labels + (size_t)(b*NG + g)*5;
    float l0=L[0], gcx=L[1], gcy=L[2], gw=L[3], gh=L[4];
    bool validgt = ((l0+gcx+gcy+gw+gh) > 0.0f);

    float gl = gcx - gw*0.5f, gr_ = gcx + gw*0.5f;
    float gt_ = gcy - gh*0.5f, gb = gcy + gh*0.5f;
    float garea = gw*gh;

    int nfg = g_nfg[b];
    const int*    cidx = g_cidx + b*NA;
    const float4* cbox = g_cbox + b*NA;
    const float4* cgeo = g_cgeo + b*NA;

    float tc[10]; int ti[10]; float tv[10]; float tu[10];
    #pragma unroll
    for (int k=0;k<10;k++){ tc[k]=3e38f; ti[k]=0x7fffffff; tv[k]=0.0f; tu[k]=0.0f; }

    for (int base = 0; base < nfg; base += TS){
        int cnt = min(TS, nfg - base);
        __syncthreads();
        for (int i = threadIdx.x; i < cnt; i += 128){
            sidx[i] = cidx[base + i];
            sbox[i] = cbox[base + i];
            sgeo[i] = cgeo[base + i];
        }
        __syncthreads();
        if (!validgt) continue;

        for (int j = lane; j < cnt; j += 32){
            float4 bb = sbox[j];
            float4 ge = sgeo[j];
            int    a  = sidx[j];
            float tlx = fmaxf(gl,  bb.x - bb.z*0.5f);
            float tly = fmaxf(gt_, bb.y - bb.w*0.5f);
            float brx = fminf(gr_, bb.x + bb.z*0.5f);
            float bry = fminf(gb,  bb.y + bb.w*0.5f);
            float iw = fmaxf(brx - tlx, 0.0f);
            float ih = fmaxf(bry - tly, 0.0f);
            float inter = iw*ih;
            float iou = inter / (garea + bb.z*bb.w - inter + 1e-12f);
            bool ib = (ge.x > gl) && (ge.x < gr_) && (ge.y > gt_) && (ge.y < gb);
            bool ic = (fabsf(ge.x - gcx) < ge.z) && (fabsf(ge.y - gcy) < ge.z);
            bool geo = ib && ic;
            float cost = ge.w - 3.0f*logf(iou + 1e-8f) + (geo ? 0.0f : 100000.0f);

            if (iou > tu[9]){
                float v = iou;
                #pragma unroll
                for (int k=0;k<10;k++){
                    if (v > tu[k]){ float t = tu[k]; tu[k] = v; v = t; }
                }
            }
            if (cost < tc[9] || (cost == tc[9] && a < ti[9])){
                float cc = cost; int ii = a; float vv = iou;
                #pragma unroll
                for (int k=0;k<10;k++){
                    bool lt = (cc < tc[k]) || (cc == tc[k] && ii < ti[k]);
                    if (lt){
                        float t0=tc[k]; tc[k]=cc; cc=t0;
                        int   t1=ti[k]; ti[k]=ii; ii=t1;
                        float t2=tv[k]; tv[k]=vv; vv=t2;
                    }
                }
            }
        }
    }

    if (!validgt) return;

    const unsigned FULL = 0xffffffffu;
    float su = 0.0f;
    #pragma unroll
    for (int r = 0; r < 10; r++){
        float bv = tu[0];
        int   bl = lane;
        #pragma unroll
        for (int off = 16; off; off >>= 1){
            float ov = __shfl_down_sync(FULL, bv, off);
            int   ol = __shfl_down_sync(FULL, bl, off);
            if (ov > bv){ bv = ov; bl = ol; }
        }
        bv = __shfl_sync(FULL, bv, 0);
        bl = __shfl_sync(FULL, bl, 0);
        if (lane == bl){
            #pragma unroll
            for (int k=0;k<9;k++) tu[k] = tu[k+1];
            tu[9] = 0.0f;
        }
        su += bv;
    }
    int dynk = (int)su;
    if (dynk < 1) dynk = 1;

    for (int r = 0; r < dynk; r++){
        float bc  = tc[0];
        int   bi  = ti[0];
        float bvv = tv[0];
        int   bl  = lane;
        #pragma unroll
        for (int off = 16; off; off >>= 1){
            float oc = __shfl_down_sync(FULL, bc,  off);
            int   oi = __shfl_down_sync(FULL, bi,  off);
            float ov = __shfl_down_sync(FULL, bvv, off);
            int   ol = __shfl_down_sync(FULL, bl,  off);
            if (oc < bc || (oc == bc && oi < bi)){ bc=oc; bi=oi; bvv=ov; bl=ol; }
        }
        bc  = __shfl_sync(FULL, bc,  0);
        bi  = __shfl_sync(FULL, bi,  0);
        bvv = __shfl_sync(FULL, bvv, 0);
        bl  = __shfl_sync(FULL, bl,  0);
        if (bc >= 1e9f) break;
        if (lane == bl){
            #pragma unroll
            for (int k=0;k<9;k++){ tc[k]=tc[k+1]; ti[k]=ti[k+1]; tv[k]=tv[k+1]; }
            tc[9] = 3e38f; ti[9] = 0x7fffffff; tv[9] = 0.0f;
        }
        if (lane == 0){
            atomicAdd(&g_cnt[b*NA + bi], 1);
            g_miou[b*NA + bi] = bvv;   // raced only when cnt>1 (then unused)
        }
    }
}

// ---------------------------------------------------------------------------
// Kernel 3: loss over compacted fg + fused last-block final reduce.
// ---------------------------------------------------------------------------
__global__ void k3_loss(const float* __restrict__ outputs,
                        const float* __restrict__ labels,
                        float* __restrict__ out){
    __shared__ float4 sgt[NG];
    __shared__ float2 scen[NG];
    __shared__ float  sarea[NG];
    __shared__ int    snv;
    __shared__ float  ssum[256];
    __shared__ int    scnt[256];
    __shared__ bool   isLast;

    int b = blockIdx.y;
    if (threadIdx.x == 0) snv = 0;
    __syncthreads();
    if (threadIdx.x < NG){
        const float* L = labels + (size_t)(b*NG + threadIdx.x)*5;
        float l0=L[0], gcx=L[1], gcy=L[2], gw=L[3], gh=L[4];
        if ((l0+gcx+gcy+gw+gh) > 0.0f){
            int p = atomicAdd(&snv, 1);
            sgt[p]   = make_float4(gcx - gw*0.5f, gcy - gh*0.5f,
                                   gcx + gw*0.5f, gcy + gh*0.5f);
            scen[p]  = make_float2(gcx, gcy);
            sarea[p] = gw*gh;
        }
    }
    __syncthreads();
    int nv = snv;

    int nfg = g_nfg[b];
    int j = blockIdx.x*blockDim.x + threadIdx.x;
    float term = 0.0f;
    int   isfg = 0;
    if (j < nfg){
        int a   = g_cidx[b*NA + j];
        int cnt = g_cnt[b*NA + a];
        if (cnt >= 1){
            isfg = 1;
            float pred_iou;
            if (cnt == 1){
                pred_iou = g_miou[b*NA + a];
            } else {
                float4 bb = g_cbox[b*NA + j];
                float4 ge = g_cgeo[b*NA + j];
                float barea = bb.z*bb.w;
                float bestc = 3e38f, besti = 0.0f;
                for (int g = 0; g < nv; g++){
                    float4 bx = sgt[g];
                    float2 cn = scen[g];
                    float tlx = fmaxf(bx.x, bb.x - bb.z*0.5f);
                    float tly = fmaxf(bx.y, bb.y - bb.w*0.5f);
                    float brx = fminf(bx.z, bb.x + bb.z*0.5f);
                    float bry = fminf(bx.w, bb.y + bb.w*0.5f);
                    float iw = fmaxf(brx - tlx, 0.0f);
                    float ih = fmaxf(bry - tly, 0.0f);
                    float inter = iw*ih;
                    float iou = inter / (sarea[g] + barea - inter + 1e-12f);
                    bool ib = (ge.x > bx.x) && (ge.x < bx.z) &&
                              (ge.y > bx.y) && (ge.y < bx.w);
                    bool ic = (fabsf(ge.x - cn.x) < ge.z) && (fabsf(ge.y - cn.y) < ge.z);
                    bool geo = ib && ic;
                    float cost = ge.w - 3.0f*logf(iou + 1e-8f) + (geo ? 0.0f : 100000.0f);
                    if (cost < bestc){ bestc = cost; besti = iou; }
                }
                pred_iou = besti;
            }
            float x = outputs[(size_t)(b*NA + a)*6 + 5];
            float sp_p = softplus(x);
            float sp_n = softplus(-x);
            term = pred_iou*sp_n + (1.0f - pred_iou)*sp_p;
        }
    }
    ssum[threadIdx.x] = term;
    scnt[threadIdx.x] = isfg;
    __syncthreads();
    for (int o = 128; o; o >>= 1){
        if (threadIdx.x < o){
            ssum[threadIdx.x] += ssum[threadIdx.x + o];
            scnt[threadIdx.x] += scnt[threadIdx.x + o];
        }
        __syncthreads();
    }
    if (threadIdx.x == 0){
        int blk = blockIdx.y*gridDim.x + blockIdx.x;
        g_psum[blk] = ssum[0];
        g_pcnt[blk] = scnt[0];
        __threadfence();
        int t = atomicAdd(&g_done, 1);
        isLast = (t == NBLK3 - 1);
    }
    __syncthreads();

    if (isLast){
        // fixed-order final reduce (deterministic)
        float s = 0.0f; int c = 0;
        for (int i = threadIdx.x; i < NBLK3; i += 256){ s += g_psum[i]; c += g_pcnt[i]; }
        ssum[threadIdx.x] = s; scnt[threadIdx.x] = c;
        __syncthreads();
        for (int o = 128; o; o >>= 1){
            if (threadIdx.x < o){
                ssum[threadIdx.x] += ssum[threadIdx.x+o];
                scnt[threadIdx.x] += scnt[threadIdx.x+o];
            }
            __syncthreads();
        }
        if (threadIdx.x == 0){
            float nf = (float)scnt[0];
            if (nf < 1.0f) nf = 1.0f;
            out[0] = ssum[0] / nf;
            g_done = 0;                     // reset for next replay
        }
        if (threadIdx.x < NB) g_nfg[threadIdx.x] = 0;   // reset for next replay
    }
}

extern "C" void kernel_launch(void* const* d_in, const int* in_sizes, int n_in,
                              void* d_out, int out_size){
    const float* outputs = (const float*)d_in[0];  // [32, 8400, 6]
    const float* labels  = (const float*)d_in[1];  // [32, 100, 5]
    const float* xs      = (const float*)d_in[2];  // [1, 8400]
    const float* ys      = (const float*)d_in[3];  // [1, 8400]
    const float* st      = (const float*)d_in[4];  // [1, 8400]

    dim3 ganchor(33, NB);
    k1_fg_compact<<<ganchor, 256>>>(outputs, labels, xs, ys, st);
    k2_assign<<<dim3(NG/4, NB), 128>>>(labels);
    k3_loss<<<ganchor, 256>>>(outputs, labels, (float*)d_out);
}

// round 5
// speedup vs baseline: 1.0306x; 1.0160x over previous
#include <cuda_runtime.h>
#include <math.h>

#define NB 32
#define NA 8400
#define NG 100
#define BA (NB*NA)
#define NBLK3 (33*32)

// ---- device scratch (static globals; zero-initialized at load) ----
__device__ int    g_cnt[BA];      // per-anchor match count
__device__ float  g_miou[BA];     // matched-pair iou (valid when cnt==1)
__device__ int    g_nfg[NB];      // per-image fg count (reset by k3 last block)
__device__ int    g_cidx[BA];     // compacted: original anchor index
__device__ float4 g_cbox[BA];     // compacted: pred bbox cxcywh
__device__ float4 g_cgeo[BA];     // compacted: xc, yc, r, clsc
__device__ float  g_psum[NBLK3];
__device__ int    g_pcnt[NBLK3];
__device__ int    g_done;         // k3 completion counter (reset by last block)

__device__ __forceinline__ float softplus(float x){
    return fmaxf(x, 0.0f) + log1pf(expf(-fabsf(x)));
}

// ---------------------------------------------------------------------------
// Kernel 1: fg mask + compaction, with per-block GT y-culling.
// ---------------------------------------------------------------------------
__global__ void k1_fg_compact(const float* __restrict__ outputs,
                              const float* __restrict__ labels,
                              const float* __restrict__ xs,
                              const float* __restrict__ ys,
                              const float* __restrict__ st){
    __shared__ float4 cgt[NG];
    __shared__ float2 ccen[NG];
    __shared__ int    scv;
    __shared__ float  rmn[8], rmx[8], rrm[8];
    __shared__ float  bymin, bymax, brmax;
    __shared__ int    wcnt[8], wbase[8], blkbase;

    int b = blockIdx.y;
    int a = blockIdx.x*blockDim.x + threadIdx.x;
    bool valid = (a < NA);
    float xc=0.f, yc=0.f, r=0.f;
    if (valid){
        float s  = st[a];
        xc = (xs[a] + 0.5f) * s;
        yc = (ys[a] + 0.5f) * s;
        r  = 2.5f * s;
    }

    int wid = threadIdx.x >> 5, lane = threadIdx.x & 31;
    {
        float mn = valid ? yc :  1e30f;
        float mx = valid ? yc : -1e30f;
        float rm = valid ? r  :  0.0f;
        #pragma unroll
        for (int off = 16; off; off >>= 1){
            mn = fminf(mn, __shfl_down_sync(0xffffffffu, mn, off));
            mx = fmaxf(mx, __shfl_down_sync(0xffffffffu, mx, off));
            rm = fmaxf(rm, __shfl_down_sync(0xffffffffu, rm, off));
        }
        if (lane == 0){ rmn[wid] = mn; rmx[wid] = mx; rrm[wid] = rm; }
    }
    if (threadIdx.x == 0) scv = 0;
    __syncthreads();
    if (threadIdx.x == 0){
        float mn = rmn[0], mx = rmx[0], rm = rrm[0];
        #pragma unroll
        for (int i = 1; i < 8; i++){
            mn = fminf(mn, rmn[i]); mx = fmaxf(mx, rmx[i]); rm = fmaxf(rm, rrm[i]);
        }
        bymin = mn; bymax = mx; brmax = rm;
    }
    __syncthreads();
    float ymin = bymin, ymax = bymax, rmaxb = brmax;

    if (threadIdx.x < NG){
        const float* L = labels + (size_t)(b*NG + threadIdx.x)*5;
        float l0=L[0], gcx=L[1], gcy=L[2], gw=L[3], gh=L[4];
        if ((l0+gcx+gcy+gw+gh) > 0.0f){
            float y0 = gcy - gh*0.5f, y1 = gcy + gh*0.5f;
            bool boxy = (ymax > y0) && (ymin < y1);
            bool ctry = (ymax > gcy - rmaxb) && (ymin < gcy + rmaxb);
            if (boxy || ctry){
                int p = atomicAdd(&scv, 1);
                cgt[p]  = make_float4(gcx - gw*0.5f, y0, gcx + gw*0.5f, y1);
                ccen[p] = make_float2(gcx, gcy);
            }
        }
    }
    __syncthreads();
    int cv = scv;

    bool fg = false;
    if (valid){
        for (int g = 0; g < cv; g++){
            float4 bx = cgt[g];
            float2 cn = ccen[g];
            bool ib = (xc > bx.x) && (xc < bx.z) && (yc > bx.y) && (yc < bx.w);
            bool ic = (fabsf(xc - cn.x) < r) && (fabsf(yc - cn.y) < r);
            if (ib || ic){ fg = true; break; }
        }
        g_cnt[b*NA + a] = 0;
    }

    unsigned ball = __ballot_sync(0xffffffffu, fg);
    if (lane == 0) wcnt[wid] = __popc(ball);
    __syncthreads();
    if (threadIdx.x == 0){
        int tot = 0;
        #pragma unroll
        for (int i = 0; i < 8; i++){ wbase[i] = tot; tot += wcnt[i]; }
        blkbase = tot ? atomicAdd(&g_nfg[b], tot) : 0;
    }
    __syncthreads();

    if (fg){
        int idx = b*NA + a;
        const float* o = outputs + (size_t)idx*6;
        float2 c2 = *(const float2*)(o);
        float2 w2 = *(const float2*)(o + 2);
        float2 oc = *(const float2*)(o + 4);
        float sig_o = 1.0f/(1.0f + expf(-oc.x));
        float sig_c = 1.0f/(1.0f + expf(-oc.y));
        float clsc = -logf(sqrtf(sig_c * sig_o) + 1e-9f);
        int pos = b*NA + blkbase + wbase[wid] + __popc(ball & ((1u << lane) - 1u));
        g_cidx[pos] = a;
        g_cbox[pos] = make_float4(c2.x, c2.y, w2.x, w2.y);
        g_cgeo[pos] = make_float4(xc, yc, r, clsc);
    }
}

// ---------------------------------------------------------------------------
// Kernel 2: 2 warps per GT (interleaved halves), barrier-free global scan,
// smem merge of two sorted top-10 lists, dyn_k + scatter by half-0 warp.
// ---------------------------------------------------------------------------
__global__ void k2_assign(const float* __restrict__ labels){
    // per-block: 2 GT slots x 2 halves x sorted top-10
    __shared__ float siou [2][20];
    __shared__ float scst [2][20];
    __shared__ int   sidw [2][20];
    __shared__ float sivw [2][20];

    int b     = blockIdx.y;
    int wid   = threadIdx.x >> 5;     // 0..3
    int gslot = wid >> 1;             // 0..1
    int half  = wid & 1;              // 0..1
    int lane  = threadIdx.x & 31;
    int g     = blockIdx.x*2 + gslot;

    const float* L = labels + (size_t)(b*NG + g)*5;
    float l0=L[0], gcx=L[1], gcy=L[2], gw=L[3], gh=L[4];
    bool validgt = ((l0+gcx+gcy+gw+gh) > 0.0f);

    float gl = gcx - gw*0.5f, gr_ = gcx + gw*0.5f;
    float gt_ = gcy - gh*0.5f, gb = gcy + gh*0.5f;
    float garea = gw*gh;

    int nfg = g_nfg[b];
    const int*    cidx = g_cidx + b*NA;
    const float4* cbox = g_cbox + b*NA;
    const float4* cgeo = g_cgeo + b*NA;

    float tc[10]; int ti[10]; float tv[10]; float tu[10];
    #pragma unroll
    for (int k=0;k<10;k++){ tc[k]=3e38f; ti[k]=0x7fffffff; tv[k]=0.0f; tu[k]=0.0f; }

    if (validgt){
        #pragma unroll 2
        for (int j = lane + half*32; j < nfg; j += 64){
            float4 bb = cbox[j];
            float4 ge = cgeo[j];
            int    a  = cidx[j];
            float tlx = fmaxf(gl,  bb.x - bb.z*0.5f);
            float tly = fmaxf(gt_, bb.y - bb.w*0.5f);
            float brx = fminf(gr_, bb.x + bb.z*0.5f);
            float bry = fminf(gb,  bb.y + bb.w*0.5f);
            float iw = fmaxf(brx - tlx, 0.0f);
            float ih = fmaxf(bry - tly, 0.0f);
            float inter = iw*ih;
            float iou = inter / (garea + bb.z*bb.w - inter + 1e-12f);
            bool ib = (ge.x > gl) && (ge.x < gr_) && (ge.y > gt_) && (ge.y < gb);
            bool ic = (fabsf(ge.x - gcx) < ge.z) && (fabsf(ge.y - gcy) < ge.z);
            bool geo = ib && ic;
            float cost = ge.w - 3.0f*logf(iou + 1e-8f) + (geo ? 0.0f : 100000.0f);

            if (iou > tu[9]){
                float v = iou;
                #pragma unroll
                for (int k=0;k<10;k++){
                    if (v > tu[k]){ float t = tu[k]; tu[k] = v; v = t; }
                }
            }
            if (cost < tc[9] || (cost == tc[9] && a < ti[9])){
                float cc = cost; int ii = a; float vv = iou;
                #pragma unroll
                for (int k=0;k<10;k++){
                    bool lt = (cc < tc[k]) || (cc == tc[k] && ii < ti[k]);
                    if (lt){
                        float t0=tc[k]; tc[k]=cc; cc=t0;
                        int   t1=ti[k]; ti[k]=ii; ii=t1;
                        float t2=tv[k]; tv[k]=vv; vv=t2;
                    }
                }
            }
        }

        const unsigned FULL = 0xffffffffu;
        // intra-warp: emit sorted top-10 ious to smem
        #pragma unroll
        for (int r = 0; r < 10; r++){
            float bv = tu[0];
            int   bl = lane;
            #pragma unroll
            for (int off = 16; off; off >>= 1){
                float ov = __shfl_down_sync(FULL, bv, off);
                int   ol = __shfl_down_sync(FULL, bl, off);
                if (ov > bv){ bv = ov; bl = ol; }
            }
            bv = __shfl_sync(FULL, bv, 0);
            bl = __shfl_sync(FULL, bl, 0);
            if (lane == bl){
                #pragma unroll
                for (int k=0;k<9;k++) tu[k] = tu[k+1];
                tu[9] = 0.0f;
            }
            if (lane == 0) siou[gslot][half*10 + r] = bv;
        }
        // intra-warp: emit sorted top-10 lex-(cost,idx) triples to smem
        #pragma unroll
        for (int r = 0; r < 10; r++){
            float bc  = tc[0];
            int   bi  = ti[0];
            float bvv = tv[0];
            int   bl  = lane;
            #pragma unroll
            for (int off = 16; off; off >>= 1){
                float oc = __shfl_down_sync(FULL, bc,  off);
                int   oi = __shfl_down_sync(FULL, bi,  off);
                float ov = __shfl_down_sync(FULL, bvv, off);
                int   ol = __shfl_down_sync(FULL, bl,  off);
                if (oc < bc || (oc == bc && oi < bi)){ bc=oc; bi=oi; bvv=ov; bl=ol; }
            }
            bc  = __shfl_sync(FULL, bc,  0);
            bi  = __shfl_sync(FULL, bi,  0);
            bvv = __shfl_sync(FULL, bvv, 0);
            bl  = __shfl_sync(FULL, bl,  0);
            if (lane == bl){
                #pragma unroll
                for (int k=0;k<9;k++){ tc[k]=tc[k+1]; ti[k]=ti[k+1]; tv[k]=tv[k+1]; }
                tc[9] = 3e38f; ti[9] = 0x7fffffff; tv[9] = 0.0f;
            }
            if (lane == 0){
                scst[gslot][half*10 + r] = bc;
                sidw[gslot][half*10 + r] = bi;
                sivw[gslot][half*10 + r] = bvv;
            }
        }
    }
    __syncthreads();

    if (half == 0 && validgt){
        const unsigned FULL = 0xffffffffu;
        // final merge: 20 candidates, one per lane, consume-by-sentinel
        float miou = (lane < 20) ? siou[gslot][lane] : 0.0f;
        float su = 0.0f;
        #pragma unroll
        for (int r = 0; r < 10; r++){
            float bv = miou;
            int   bl = lane;
            #pragma unroll
            for (int off = 16; off; off >>= 1){
                float ov = __shfl_down_sync(FULL, bv, off);
                int   ol = __shfl_down_sync(FULL, bl, off);
                if (ov > bv){ bv = ov; bl = ol; }
            }
            bv = __shfl_sync(FULL, bv, 0);
            bl = __shfl_sync(FULL, bl, 0);
            if (lane == bl) miou = -1.0f;
            su += fmaxf(bv, 0.0f);
        }
        int dynk = (int)su;
        if (dynk < 1) dynk = 1;

        float mc = (lane < 20) ? scst[gslot][lane] : 3e38f;
        int   mi = (lane < 20) ? sidw[gslot][lane] : 0x7fffffff;
        float mv = (lane < 20) ? sivw[gslot][lane] : 0.0f;
        for (int r = 0; r < dynk; r++){
            float bc  = mc;
            int   bi  = mi;
            float bvv = mv;
            int   bl  = lane;
            #pragma unroll
            for (int off = 16; off; off >>= 1){
                float oc = __shfl_down_sync(FULL, bc,  off);
                int   oi = __shfl_down_sync(FULL, bi,  off);
                float ov = __shfl_down_sync(FULL, bvv, off);
                int   ol = __shfl_down_sync(FULL, bl,  off);
                if (oc < bc || (oc == bc && oi < bi)){ bc=oc; bi=oi; bvv=ov; bl=ol; }
            }
            bc  = __shfl_sync(FULL, bc,  0);
            bi  = __shfl_sync(FULL, bi,  0);
            bvv = __shfl_sync(FULL, bvv, 0);
            bl  = __shfl_sync(FULL, bl,  0);
            if (bc >= 1e9f) break;
            if (lane == bl){ mc = 3e38f; mi = 0x7fffffff; }
            if (lane == 0){
                atomicAdd(&g_cnt[b*NA + bi], 1);
                g_miou[b*NA + bi] = bvv;   // raced only when cnt>1 (then unused)
            }
        }
    }
}

// ---------------------------------------------------------------------------
// Kernel 3: loss over compacted fg + fused last-block final reduce.
// ---------------------------------------------------------------------------
__global__ void k3_loss(const float* __restrict__ outputs,
                        const float* __restrict__ labels,
                        float* __restrict__ out){
    __shared__ float4 sgt[NG];
    __shared__ float2 scen[NG];
    __shared__ float  sarea[NG];
    __shared__ int    snv;
    __shared__ float  ssum[256];
    __shared__ int    scnt[256];
    __shared__ bool   isLast;

    int b = blockIdx.y;
    if (threadIdx.x == 0) snv = 0;
    __syncthreads();
    if (threadIdx.x < NG){
        const float* L = labels + (size_t)(b*NG + threadIdx.x)*5;
        float l0=L[0], gcx=L[1], gcy=L[2], gw=L[3], gh=L[4];
        if ((l0+gcx+gcy+gw+gh) > 0.0f){
            int p = atomicAdd(&snv, 1);
            sgt[p]   = make_float4(gcx - gw*0.5f, gcy - gh*0.5f,
                                   gcx + gw*0.5f, gcy + gh*0.5f);
            scen[p]  = make_float2(gcx, gcy);
            sarea[p] = gw*gh;
        }
    }
    __syncthreads();
    int nv = snv;

    int nfg = g_nfg[b];
    int j = blockIdx.x*blockDim.x + threadIdx.x;
    float term = 0.0f;
    int   isfg = 0;
    if (j < nfg){
        int a   = g_cidx[b*NA + j];
        int cnt = g_cnt[b*NA + a];
        if (cnt >= 1){
            isfg = 1;
            float pred_iou;
            if (cnt == 1){
                pred_iou = g_miou[b*NA + a];
            } else {
                float4 bb = g_cbox[b*NA + j];
                float4 ge = g_cgeo[b*NA + j];
                float barea = bb.z*bb.w;
                float bestc = 3e38f, besti = 0.0f;
                for (int g = 0; g < nv; g++){
                    float4 bx = sgt[g];
                    float2 cn = scen[g];
                    float tlx = fmaxf(bx.x, bb.x - bb.z*0.5f);
                    float tly = fmaxf(bx.y, bb.y - bb.w*0.5f);
                    float brx = fminf(bx.z, bb.x + bb.z*0.5f);
                    float bry = fminf(bx.w, bb.y + bb.w*0.5f);
                    float iw = fmaxf(brx - tlx, 0.0f);
                    float ih = fmaxf(bry - tly, 0.0f);
                    float inter = iw*ih;
                    float iou = inter / (sarea[g] + barea - inter + 1e-12f);
                    bool ib = (ge.x > bx.x) && (ge.x < bx.z) &&
                              (ge.y > bx.y) && (ge.y < bx.w);
                    bool ic = (fabsf(ge.x - cn.x) < ge.z) && (fabsf(ge.y - cn.y) < ge.z);
                    bool geo = ib && ic;
                    float cost = ge.w - 3.0f*logf(iou + 1e-8f) + (geo ? 0.0f : 100000.0f);
                    if (cost < bestc){ bestc = cost; besti = iou; }
                }
                pred_iou = besti;
            }
            float x = outputs[(size_t)(b*NA + a)*6 + 5];
            float sp_p = softplus(x);
            float sp_n = softplus(-x);
            term = pred_iou*sp_n + (1.0f - pred_iou)*sp_p;
        }
    }
    ssum[threadIdx.x] = term;
    scnt[threadIdx.x] = isfg;
    __syncthreads();
    for (int o = 128; o; o >>= 1){
        if (threadIdx.x < o){
            ssum[threadIdx.x] += ssum[threadIdx.x + o];
            scnt[threadIdx.x] += scnt[threadIdx.x + o];
        }
        __syncthreads();
    }
    if (threadIdx.x == 0){
        int blk = blockIdx.y*gridDim.x + blockIdx.x;
        g_psum[blk] = ssum[0];
        g_pcnt[blk] = scnt[0];
        __threadfence();
        int t = atomicAdd(&g_done, 1);
        isLast = (t == NBLK3 - 1);
    }
    __syncthreads();

    if (isLast){
        float s = 0.0f; int c = 0;
        for (int i = threadIdx.x; i < NBLK3; i += 256){ s += g_psum[i]; c += g_pcnt[i]; }
        ssum[threadIdx.x] = s; scnt[threadIdx.x] = c;
        __syncthreads();
        for (int o = 128; o; o >>= 1){
            if (threadIdx.x < o){
                ssum[threadIdx.x] += ssum[threadIdx.x+o];
                scnt[threadIdx.x] += scnt[threadIdx.x+o];
            }
            __syncthreads();
        }
        if (threadIdx.x == 0){
            float nf = (float)scnt[0];
            if (nf < 1.0f) nf = 1.0f;
            out[0] = ssum[0] / nf;
            g_done = 0;
        }
        if (threadIdx.x < NB) g_nfg[threadIdx.x] = 0;
    }
}

extern "C" void kernel_launch(void* const* d_in, const int* in_sizes, int n_in,
                              void* d_out, int out_size){
    const float* outputs = (const float*)d_in[0];  // [32, 8400, 6]
    const float* labels  = (const float*)d_in[1];  // [32, 100, 5]
    const float* xs      = (const float*)d_in[2];  // [1, 8400]
    const float* ys      = (const float*)d_in[3];  // [1, 8400]
    const float* st      = (const float*)d_in[4];  // [1, 8400]

    dim3 ganchor(33, NB);
    k1_fg_compact<<<ganchor, 256>>>(outputs, labels, xs, ys, st);
    k2_assign<<<dim3(NG/2, NB), 128>>>(labels);
    k3_loss<<<ganchor, 256>>>(outputs, labels, (float*)d_out);
}

// round 6
// speedup vs baseline: 1.0328x; 1.0022x over previous
#include <cuda_runtime.h>
#include <math.h>

#define NB 32
#define NA 8400
#define NG 100
#define BA (NB*NA)
#define NBLK3 (33*32)
#define K2W 8      // GTs (warps) per k2 block
#define K2T 256    // fg tile entries

// ---- device scratch (static globals; zero-initialized at load) ----
__device__ int    g_cnt[BA];
__device__ float  g_miou[BA];
__device__ int    g_nfg[NB];
__device__ int    g_cidx[BA];
__device__ float4 g_cbox[BA];
__device__ float4 g_cgeo[BA];
__device__ float  g_psum[NBLK3];
__device__ int    g_pcnt[NBLK3];
__device__ int    g_done;

__device__ __forceinline__ float softplus(float x){
    return fmaxf(x, 0.0f) + log1pf(expf(-fabsf(x)));
}

// ---------------------------------------------------------------------------
// Kernel 1: fg mask + compaction, with per-block GT y-culling.
// ---------------------------------------------------------------------------
__global__ void k1_fg_compact(const float* __restrict__ outputs,
                              const float* __restrict__ labels,
                              const float* __restrict__ xs,
                              const float* __restrict__ ys,
                              const float* __restrict__ st){
    __shared__ float4 cgt[NG];
    __shared__ float2 ccen[NG];
    __shared__ int    scv;
    __shared__ float  rmn[8], rmx[8], rrm[8];
    __shared__ float  bymin, bymax, brmax;
    __shared__ int    wcnt[8], wbase[8], blkbase;

    int b = blockIdx.y;
    int a = blockIdx.x*blockDim.x + threadIdx.x;
    bool valid = (a < NA);
    float xc=0.f, yc=0.f, r=0.f;
    if (valid){
        float s  = st[a];
        xc = (xs[a] + 0.5f) * s;
        yc = (ys[a] + 0.5f) * s;
        r  = 2.5f * s;
    }

    int wid = threadIdx.x >> 5, lane = threadIdx.x & 31;
    {
        float mn = valid ? yc :  1e30f;
        float mx = valid ? yc : -1e30f;
        float rm = valid ? r  :  0.0f;
        #pragma unroll
        for (int off = 16; off; off >>= 1){
            mn = fminf(mn, __shfl_down_sync(0xffffffffu, mn, off));
            mx = fmaxf(mx, __shfl_down_sync(0xffffffffu, mx, off));
            rm = fmaxf(rm, __shfl_down_sync(0xffffffffu, rm, off));
        }
        if (lane == 0){ rmn[wid] = mn; rmx[wid] = mx; rrm[wid] = rm; }
    }
    if (threadIdx.x == 0) scv = 0;
    __syncthreads();
    if (threadIdx.x == 0){
        float mn = rmn[0], mx = rmx[0], rm = rrm[0];
        #pragma unroll
        for (int i = 1; i < 8; i++){
            mn = fminf(mn, rmn[i]); mx = fmaxf(mx, rmx[i]); rm = fmaxf(rm, rrm[i]);
        }
        bymin = mn; bymax = mx; brmax = rm;
    }
    __syncthreads();
    float ymin = bymin, ymax = bymax, rmaxb = brmax;

    if (threadIdx.x < NG){
        const float* L = labels + (size_t)(b*NG + threadIdx.x)*5;
        float l0=L[0], gcx=L[1], gcy=L[2], gw=L[3], gh=L[4];
        if ((l0+gcx+gcy+gw+gh) > 0.0f){
            float y0 = gcy - gh*0.5f, y1 = gcy + gh*0.5f;
            bool boxy = (ymax > y0) && (ymin < y1);
            bool ctry = (ymax > gcy - rmaxb) && (ymin < gcy + rmaxb);
            if (boxy || ctry){
                int p = atomicAdd(&scv, 1);
                cgt[p]  = make_float4(gcx - gw*0.5f, y0, gcx + gw*0.5f, y1);
                ccen[p] = make_float2(gcx, gcy);
            }
        }
    }
    __syncthreads();
    int cv = scv;

    bool fg = false;
    if (valid){
        for (int g = 0; g < cv; g++){
            float4 bx = cgt[g];
            float2 cn = ccen[g];
            bool ib = (xc > bx.x) && (xc < bx.z) && (yc > bx.y) && (yc < bx.w);
            bool ic = (fabsf(xc - cn.x) < r) && (fabsf(yc - cn.y) < r);
            if (ib || ic){ fg = true; break; }
        }
        g_cnt[b*NA + a] = 0;
    }

    unsigned ball = __ballot_sync(0xffffffffu, fg);
    if (lane == 0) wcnt[wid] = __popc(ball);
    __syncthreads();
    if (threadIdx.x == 0){
        int tot = 0;
        #pragma unroll
        for (int i = 0; i < 8; i++){ wbase[i] = tot; tot += wcnt[i]; }
        blkbase = tot ? atomicAdd(&g_nfg[b], tot) : 0;
    }
    __syncthreads();

    if (fg){
        int idx = b*NA + a;
        const float* o = outputs + (size_t)idx*6;
        float2 c2 = *(const float2*)(o);
        float2 w2 = *(const float2*)(o + 2);
        float2 oc = *(const float2*)(o + 4);
        float sig_o = 1.0f/(1.0f + expf(-oc.x));
        float sig_c = 1.0f/(1.0f + expf(-oc.y));
        float clsc = -logf(sqrtf(sig_c * sig_o) + 1e-9f);
        int pos = b*NA + blkbase + wbase[wid] + __popc(ball & ((1u << lane) - 1u));
        g_cidx[pos] = a;
        g_cbox[pos] = make_float4(c2.x, c2.y, w2.x, w2.y);
        g_cgeo[pos] = make_float4(xc, yc, r, clsc);
    }
}

// ---------------------------------------------------------------------------
// Kernel 2: 8 warps/block = 8 GTs of one image; fg list streamed once per
// block through double-buffered smem tiles with register prefetch.
// ---------------------------------------------------------------------------
__global__ void k2_assign(const float* __restrict__ labels){
    __shared__ int    sidx[2][K2T];
    __shared__ float4 sbox[2][K2T];
    __shared__ float4 sgeo[2][K2T];

    int b    = blockIdx.y;
    int wid  = threadIdx.x >> 5;
    int lane = threadIdx.x & 31;
    int g    = blockIdx.x*K2W + wid;

    bool validgt = false;
    float gcx=0,gcy=0,gl=0,gr_=0,gt_=0,gb=0,garea=0;
    if (g < NG){
        const float* L = labels + (size_t)(b*NG + g)*5;
        float l0=L[0], cx=L[1], cy=L[2], w=L[3], h=L[4];
        if ((l0+cx+cy+w+h) > 0.0f){
            validgt = true;
            gcx=cx; gcy=cy;
            gl=cx-w*0.5f; gr_=cx+w*0.5f; gt_=cy-h*0.5f; gb=cy+h*0.5f;
            garea=w*h;
        }
    }

    int nfg = g_nfg[b];
    const int*    cidx = g_cidx + b*NA;
    const float4* cbox = g_cbox + b*NA;
    const float4* cgeo = g_cgeo + b*NA;
    int ntile = (nfg + K2T - 1) / K2T;

    float tc[10]; int ti[10]; float tv[10]; float tu[10];
    #pragma unroll
    for (int k=0;k<10;k++){ tc[k]=3e38f; ti[k]=0x7fffffff; tv[k]=0.0f; tu[k]=0.0f; }

    // prologue: stage tile 0
    if (threadIdx.x < nfg){
        sidx[0][threadIdx.x] = cidx[threadIdx.x];
        sbox[0][threadIdx.x] = cbox[threadIdx.x];
        sgeo[0][threadIdx.x] = cgeo[threadIdx.x];
    }
    __syncthreads();

    for (int t = 0; t < ntile; t++){
        int cur = t & 1, nxt = cur ^ 1;
        int base = t*K2T;
        int cnt = min(K2T, nfg - base);

        // prefetch next tile into registers (LDGs issued, latency hidden by compute)
        int pv = 0; int pIdx; float4 pBox, pGeo;
        int nj = base + K2T + threadIdx.x;
        if (t+1 < ntile && nj < nfg){
            pv = 1;
            pIdx = cidx[nj];
            pBox = cbox[nj];
            pGeo = cgeo[nj];
        }

        if (validgt){
            for (int j = lane; j < cnt; j += 32){
                float4 bb = sbox[cur][j];
                float4 ge = sgeo[cur][j];
                int    a  = sidx[cur][j];
                float tlx = fmaxf(gl,  bb.x - bb.z*0.5f);
                float tly = fmaxf(gt_, bb.y - bb.w*0.5f);
                float brx = fminf(gr_, bb.x + bb.z*0.5f);
                float bry = fminf(gb,  bb.y + bb.w*0.5f);
                float iw = fmaxf(brx - tlx, 0.0f);
                float ih = fmaxf(bry - tly, 0.0f);
                float inter = iw*ih;
                float iou = inter / (garea + bb.z*bb.w - inter + 1e-12f);
                bool ib = (ge.x > gl) && (ge.x < gr_) && (ge.y > gt_) && (ge.y < gb);
                bool ic = (fabsf(ge.x - gcx) < ge.z) && (fabsf(ge.y - gcy) < ge.z);
                bool geo = ib && ic;
                float cost = ge.w - 3.0f*logf(iou + 1e-8f) + (geo ? 0.0f : 100000.0f);

                if (iou > tu[9]){
                    float v = iou;
                    #pragma unroll
                    for (int k=0;k<10;k++){
                        if (v > tu[k]){ float tmp = tu[k]; tu[k] = v; v = tmp; }
                    }
                }
                if (cost < tc[9] || (cost == tc[9] && a < ti[9])){
                    float cc = cost; int ii = a; float vv = iou;
                    #pragma unroll
                    for (int k=0;k<10;k++){
                        bool lt = (cc < tc[k]) || (cc == tc[k] && ii < ti[k]);
                        if (lt){
                            float t0=tc[k]; tc[k]=cc; cc=t0;
                            int   t1=ti[k]; ti[k]=ii; ii=t1;
                            float t2=tv[k]; tv[k]=vv; vv=t2;
                        }
                    }
                }
            }
        }

        // store prefetched tile (readers of nxt finished before end-of-(t-1) sync)
        if (pv){
            sidx[nxt][threadIdx.x] = pIdx;
            sbox[nxt][threadIdx.x] = pBox;
            sgeo[nxt][threadIdx.x] = pGeo;
        }
        __syncthreads();
    }

    if (!validgt) return;

    const unsigned FULL = 0xffffffffu;
    float su = 0.0f;
    #pragma unroll
    for (int r = 0; r < 10; r++){
        float bv = tu[0];
        int   bl = lane;
        #pragma unroll
        for (int off = 16; off; off >>= 1){
            float ov = __shfl_down_sync(FULL, bv, off);
            int   ol = __shfl_down_sync(FULL, bl, off);
            if (ov > bv){ bv = ov; bl = ol; }
        }
        bv = __shfl_sync(FULL, bv, 0);
        bl = __shfl_sync(FULL, bl, 0);
        if (lane == bl){
            #pragma unroll
            for (int k=0;k<9;k++) tu[k] = tu[k+1];
            tu[9] = 0.0f;
        }
        su += bv;
    }
    int dynk = (int)su;
    if (dynk < 1) dynk = 1;

    for (int r = 0; r < dynk; r++){
        float bc  = tc[0];
        int   bi  = ti[0];
        float bvv = tv[0];
        int   bl  = lane;
        #pragma unroll
        for (int off = 16; off; off >>= 1){
            float oc = __shfl_down_sync(FULL, bc,  off);
            int   oi = __shfl_down_sync(FULL, bi,  off);
            float ov = __shfl_down_sync(FULL, bvv, off);
            int   ol = __shfl_down_sync(FULL, bl,  off);
            if (oc < bc || (oc == bc && oi < bi)){ bc=oc; bi=oi; bvv=ov; bl=ol; }
        }
        bc  = __shfl_sync(FULL, bc,  0);
        bi  = __shfl_sync(FULL, bi,  0);
        bvv = __shfl_sync(FULL, bvv, 0);
        bl  = __shfl_sync(FULL, bl,  0);
        if (bc >= 1e9f) break;
        if (lane == bl){
            #pragma unroll
            for (int k=0;k<9;k++){ tc[k]=tc[k+1]; ti[k]=ti[k+1]; tv[k]=tv[k+1]; }
            tc[9] = 3e38f; ti[9] = 0x7fffffff; tv[9] = 0.0f;
        }
        if (lane == 0){
            atomicAdd(&g_cnt[b*NA + bi], 1);
            g_miou[b*NA + bi] = bvv;
        }
    }
}

// ---------------------------------------------------------------------------
// Kernel 3: loss over compacted fg + fused last-block final reduce.
// ---------------------------------------------------------------------------
__global__ void k3_loss(const float* __restrict__ outputs,
                        const float* __restrict__ labels,
                        float* __restrict__ out){
    __shared__ float4 sgt[NG];
    __shared__ float2 scen[NG];
    __shared__ float  sarea[NG];
    __shared__ int    snv;
    __shared__ float  ssum[256];
    __shared__ int    scnt[256];
    __shared__ bool   isLast;

    int b = blockIdx.y;
    if (threadIdx.x == 0) snv = 0;
    __syncthreads();
    if (threadIdx.x < NG){
        const float* L = labels + (size_t)(b*NG + threadIdx.x)*5;
        float l0=L[0], gcx=L[1], gcy=L[2], gw=L[3], gh=L[4];
        if ((l0+gcx+gcy+gw+gh) > 0.0f){
            int p = atomicAdd(&snv, 1);
            sgt[p]   = make_float4(gcx - gw*0.5f, gcy - gh*0.5f,
                                   gcx + gw*0.5f, gcy + gh*0.5f);
            scen[p]  = make_float2(gcx, gcy);
            sarea[p] = gw*gh;
        }
    }
    __syncthreads();
    int nv = snv;

    int nfg = g_nfg[b];
    int j = blockIdx.x*blockDim.x + threadIdx.x;
    float term = 0.0f;
    int   isfg = 0;
    if (j < nfg){
        int a   = g_cidx[b*NA + j];
        int cnt = g_cnt[b*NA + a];
        if (cnt >= 1){
            isfg = 1;
            float pred_iou;
            if (cnt == 1){
                pred_iou = g_miou[b*NA + a];
            } else {
                float4 bb = g_cbox[b*NA + j];
                float4 ge = g_cgeo[b*NA + j];
                float barea = bb.z*bb.w;
                float bestc = 3e38f, besti = 0.0f;
                for (int g = 0; g < nv; g++){
                    float4 bx = sgt[g];
                    float2 cn = scen[g];
                    float tlx = fmaxf(bx.x, bb.x - bb.z*0.5f);
                    float tly = fmaxf(bx.y, bb.y - bb.w*0.5f);
                    float brx = fminf(bx.z, bb.x + bb.z*0.5f);
                    float bry = fminf(bx.w, bb.y + bb.w*0.5f);
                    float iw = fmaxf(brx - tlx, 0.0f);
                    float ih = fmaxf(bry - tly, 0.0f);
                    float inter = iw*ih;
                    float iou = inter / (sarea[g] + barea - inter + 1e-12f);
                    bool ib = (ge.x > bx.x) && (ge.x < bx.z) &&
                              (ge.y > bx.y) && (ge.y < bx.w);
                    bool ic = (fabsf(ge.x - cn.x) < ge.z) && (fabsf(ge.y - cn.y) < ge.z);
                    bool geo = ib && ic;
                    float cost = ge.w - 3.0f*logf(iou + 1e-8f) + (geo ? 0.0f : 100000.0f);
                    if (cost < bestc){ bestc = cost; besti = iou; }
                }
                pred_iou = besti;
            }
            float x = outputs[(size_t)(b*NA + a)*6 + 5];
            float sp_p = softplus(x);
            float sp_n = softplus(-x);
            term = pred_iou*sp_n + (1.0f - pred_iou)*sp_p;
        }
    }
    ssum[threadIdx.x] = term;
    scnt[threadIdx.x] = isfg;
    __syncthreads();
    for (int o = 128; o; o >>= 1){
        if (threadIdx.x < o){
            ssum[threadIdx.x] += ssum[threadIdx.x + o];
            scnt[threadIdx.x] += scnt[threadIdx.x + o];
        }
        __syncthreads();
    }
    if (threadIdx.x == 0){
        int blk = blockIdx.y*gridDim.x + blockIdx.x;
        g_psum[blk] = ssum[0];
        g_pcnt[blk] = scnt[0];
        __threadfence();
        int t = atomicAdd(&g_done, 1);
        isLast = (t == NBLK3 - 1);
    }
    __syncthreads();

    if (isLast){
        float s = 0.0f; int c = 0;
        for (int i = threadIdx.x; i < NBLK3; i += 256){ s += g_psum[i]; c += g_pcnt[i]; }
        ssum[threadIdx.x] = s; scnt[threadIdx.x] = c;
        __syncthreads();
        for (int o = 128; o; o >>= 1){
            if (threadIdx.x < o){
                ssum[threadIdx.x] += ssum[threadIdx.x+o];
                scnt[threadIdx.x] += scnt[threadIdx.x+o];
            }
            __syncthreads();
        }
        if (threadIdx.x == 0){
            float nf = (float)scnt[0];
            if (nf < 1.0f) nf = 1.0f;
            out[0] = ssum[0] / nf;
            g_done = 0;
        }
        if (threadIdx.x < NB) g_nfg[threadIdx.x] = 0;
    }
}

extern "C" void kernel_launch(void* const* d_in, const int* in_sizes, int n_in,
                              void* d_out, int out_size){
    const float* outputs = (const float*)d_in[0];  // [32, 8400, 6]
    const float* labels  = (const float*)d_in[1];  // [32, 100, 5]
    const float* xs      = (const float*)d_in[2];  // [1, 8400]
    const float* ys      = (const float*)d_in[3];  // [1, 8400]
    const float* st      = (const float*)d_in[4];  // [1, 8400]

    dim3 ganchor(33, NB);
    k1_fg_compact<<<ganchor, 256>>>(outputs, labels, xs, ys, st);
    k2_assign<<<dim3((NG + K2W - 1)/K2W, NB), 256>>>(labels);
    k3_loss<<<ganchor, 256>>>(outputs, labels, (float*)d_out);
}